// round 3
// baseline (speedup 1.0000x reference)
#include <cuda_runtime.h>
#include <math.h>

#define NSEG 440
#define NCH  2112
#define HW   65536
#define NH   1024
#define ND   32

// ---------------- scratch (device globals; no allocation allowed) -------------
__device__ float g_fmT[(size_t)HW * NCH];   // 553MB transposed feature maps
__device__ int   g_order[HW];
__device__ int   g_off[NSEG + 1];
__device__ int   g_pos[NSEG];
__device__ int   g_cnt[NSEG];
__device__ int   g_hist[NSEG * 3];
__device__ float g_feat[NSEG * NCH];
__device__ float g_fn[NSEG * NCH];
__device__ float g_h1[NSEG * NH];
__device__ float g_h2[NSEG * NH];
__device__ int   g_lab[NSEG];
__device__ float g_aff[NSEG * NSEG];

// ---------------- zero small scratch (must run every replay) ------------------
__global__ void k_zero() {
    int i = blockIdx.x * blockDim.x + threadIdx.x;
    if (i < NSEG)     { g_cnt[i] = 0; g_pos[i] = 0; }
    if (i < NSEG * 3) g_hist[i] = 0;
}

// ---------------- per-segment pixel counts + class histogram ------------------
__global__ void k_hist(const int* __restrict__ sp, const int* __restrict__ y) {
    int p = blockIdx.x * blockDim.x + threadIdx.x;
    if (p < HW) {
        int s = sp[p];
        atomicAdd(&g_cnt[s], 1);
        atomicAdd(&g_hist[s * 3 + y[p]], 1);
    }
}

// ---------------- exclusive scan of counts -> segment offsets -----------------
__global__ void k_scan() {
    __shared__ int s[512];
    int t = threadIdx.x;
    s[t] = (t < NSEG) ? g_cnt[t] : 0;
    __syncthreads();
    for (int o = 1; o < 512; o <<= 1) {
        int v = (t >= o) ? s[t - o] : 0;
        __syncthreads();
        s[t] += v;
        __syncthreads();
    }
    if (t < NSEG) g_off[t + 1] = s[t];
    if (t == 0)   g_off[0] = 0;
}

// ---------------- scatter pixel indices into segment-sorted order -------------
__global__ void k_scatter(const int* __restrict__ sp) {
    int p = blockIdx.x * blockDim.x + threadIdx.x;
    if (p < HW) {
        int s = sp[p];
        int idx = g_off[s] + atomicAdd(&g_pos[s], 1);
        g_order[idx] = p;
    }
}

// ---------------- tiled transpose: fm (C x P) -> g_fmT (P x C) ----------------
__global__ __launch_bounds__(256) void k_tr(const float* __restrict__ fm) {
    __shared__ float s[32][33];
    int tx = threadIdx.x, ty = threadIdx.y;          // (32, 8)
    int p0 = blockIdx.x * 32, c0 = blockIdx.y * 32;
#pragma unroll
    for (int j = 0; j < 32; j += 8)
        s[ty + j][tx] = fm[(size_t)(c0 + ty + j) * HW + p0 + tx];
    __syncthreads();
#pragma unroll
    for (int j = 0; j < 32; j += 8)
        g_fmT[(size_t)(p0 + ty + j) * NCH + c0 + tx] = s[tx][ty + j];
}

// ---------------- pooling: block per segment, coalesced row accumulation ------
// Also fuses feat = sum/cnt and fn = feat/||feat||.
__global__ __launch_bounds__(256) void k_pool() {
    int s = blockIdx.x;
    int t = threadIdx.x;
    int beg = g_off[s], end = g_off[s + 1];

    float4 a0 = make_float4(0.f, 0.f, 0.f, 0.f);
    float4 a1 = a0;
    float4 a2 = a0;

    for (int j = beg; j < end; ++j) {
        const float4* row = (const float4*)(g_fmT + (size_t)__ldg(&g_order[j]) * NCH);
        float4 r0 = __ldg(&row[t]);
        float4 r1 = __ldg(&row[t + 256]);
        a0.x += r0.x; a0.y += r0.y; a0.z += r0.z; a0.w += r0.w;
        a1.x += r1.x; a1.y += r1.y; a1.z += r1.z; a1.w += r1.w;
        if (t < 16) {
            float4 r2 = __ldg(&row[t + 512]);
            a2.x += r2.x; a2.y += r2.y; a2.z += r2.z; a2.w += r2.w;
        }
    }

    float cnt = (float)(end - beg);
    if (cnt < 1.f) cnt = 1.f;
    float inv = 1.f / cnt;
    a0.x *= inv; a0.y *= inv; a0.z *= inv; a0.w *= inv;
    a1.x *= inv; a1.y *= inv; a1.z *= inv; a1.w *= inv;
    a2.x *= inv; a2.y *= inv; a2.z *= inv; a2.w *= inv;

    float4* gf = (float4*)(g_feat + (size_t)s * NCH);
    gf[t] = a0;
    gf[t + 256] = a1;
    if (t < 16) gf[t + 512] = a2;

    float sq = a0.x * a0.x + a0.y * a0.y + a0.z * a0.z + a0.w * a0.w
             + a1.x * a1.x + a1.y * a1.y + a1.z * a1.z + a1.w * a1.w;
    if (t < 16)
        sq += a2.x * a2.x + a2.y * a2.y + a2.z * a2.z + a2.w * a2.w;

    __shared__ float red[256];
    red[t] = sq;
    __syncthreads();
    for (int o = 128; o; o >>= 1) {
        if (t < o) red[t] += red[t + o];
        __syncthreads();
    }
    float nrm = sqrtf(red[0]);
    float rinv = 1.f / nrm;

    float4* gn = (float4*)(g_fn + (size_t)s * NCH);
    a0.x *= rinv; a0.y *= rinv; a0.z *= rinv; a0.w *= rinv;
    a1.x *= rinv; a1.y *= rinv; a1.z *= rinv; a1.w *= rinv;
    a2.x *= rinv; a2.y *= rinv; a2.z *= rinv; a2.w *= rinv;
    gn[t] = a0;
    gn[t + 256] = a1;
    if (t < 16) gn[t + 512] = a2;
}

// ---------------- labels from histogram (exact int replication of reference) --
__global__ void k_lab() {
    int s = blockIdx.x * blockDim.x + threadIdx.x;
    if (s < NSEG) {
        int h0 = g_hist[s * 3 + 0];
        int h1 = g_hist[s * 3 + 1];
        int h2 = g_hist[s * 3 + 2];
        int l = 0, best = h0;
        if (h1 > best) { best = h1; l = 1; }   // argmax, first index on ties
        if (h2 > best) { best = h2; l = 2; }
        if (l == 0) l = (h2 > h1) ? 2 : ((h1 > h2) ? 1 : 0);
        g_lab[s] = l;
    }
}

// ---------------- fp32 GEMM: C = relu(A @ B + bias), A:MxK, B:KxN row-major ----
__global__ __launch_bounds__(256) void k_gemm_relu(
    const float* __restrict__ A, const float* __restrict__ B,
    const float* __restrict__ bias, float* __restrict__ Cout,
    int M, int N, int K)
{
    __shared__ float As[16][64];
    __shared__ float Bs[16][64];
    int tx = threadIdx.x, ty = threadIdx.y;
    int tid = ty * 16 + tx;
    int row0 = blockIdx.y * 64;
    int col0 = blockIdx.x * 64;

    float acc[4][4] = {};

    int aRow = tid >> 2;
    int aCol = (tid & 3) * 4;
    int bRow = tid >> 4;
    int bCol = (tid & 15) * 4;

    for (int k0 = 0; k0 < K; k0 += 16) {
        float4 av;
        int gm = row0 + aRow;
        if (gm < M) av = *(const float4*)&A[(size_t)gm * K + k0 + aCol];
        else        av = make_float4(0.f, 0.f, 0.f, 0.f);
        As[aCol + 0][aRow] = av.x;
        As[aCol + 1][aRow] = av.y;
        As[aCol + 2][aRow] = av.z;
        As[aCol + 3][aRow] = av.w;

        float4 bv = *(const float4*)&B[(size_t)(k0 + bRow) * N + col0 + bCol];
        *(float4*)&Bs[bRow][bCol] = bv;
        __syncthreads();

#pragma unroll
        for (int kk = 0; kk < 16; ++kk) {
            float4 a = *(float4*)&As[kk][ty * 4];
            float4 b = *(float4*)&Bs[kk][tx * 4];
            float aa[4] = {a.x, a.y, a.z, a.w};
            float bb[4] = {b.x, b.y, b.z, b.w};
#pragma unroll
            for (int i = 0; i < 4; ++i)
#pragma unroll
                for (int j = 0; j < 4; ++j)
                    acc[i][j] += aa[i] * bb[j];
        }
        __syncthreads();
    }

#pragma unroll
    for (int i = 0; i < 4; ++i) {
        int m = row0 + ty * 4 + i;
        if (m < M) {
#pragma unroll
            for (int j = 0; j < 4; ++j) {
                int n = col0 + tx * 4 + j;
                float v = acc[i][j] + bias[n];
                Cout[(size_t)m * N + n] = fmaxf(v, 0.f);
            }
        }
    }
}

// ---------------- affinity: aff[i][j] = expf(-dot(fn_i, fn_j)) -----------------
__global__ __launch_bounds__(256) void k_aff() {
    __shared__ float As[16][64];
    __shared__ float Bs[16][64];
    int tx = threadIdx.x, ty = threadIdx.y;
    int tid = ty * 16 + tx;
    int i0 = blockIdx.y * 64;
    int j0 = blockIdx.x * 64;

    float acc[4][4] = {};

    int aRow = tid >> 2;
    int aCol = (tid & 3) * 4;

    for (int k0 = 0; k0 < NCH; k0 += 16) {
        int gi = i0 + aRow;
        int gj = j0 + aRow;
        float4 av = (gi < NSEG) ? *(const float4*)&g_fn[(size_t)gi * NCH + k0 + aCol]
                                : make_float4(0.f, 0.f, 0.f, 0.f);
        float4 bv = (gj < NSEG) ? *(const float4*)&g_fn[(size_t)gj * NCH + k0 + aCol]
                                : make_float4(0.f, 0.f, 0.f, 0.f);
        As[aCol + 0][aRow] = av.x; As[aCol + 1][aRow] = av.y;
        As[aCol + 2][aRow] = av.z; As[aCol + 3][aRow] = av.w;
        Bs[aCol + 0][aRow] = bv.x; Bs[aCol + 1][aRow] = bv.y;
        Bs[aCol + 2][aRow] = bv.z; Bs[aCol + 3][aRow] = bv.w;
        __syncthreads();

#pragma unroll
        for (int kk = 0; kk < 16; ++kk) {
            float4 a = *(float4*)&As[kk][ty * 4];
            float4 b = *(float4*)&Bs[kk][tx * 4];
            float aa[4] = {a.x, a.y, a.z, a.w};
            float bb[4] = {b.x, b.y, b.z, b.w};
#pragma unroll
            for (int i = 0; i < 4; ++i)
#pragma unroll
                for (int j = 0; j < 4; ++j)
                    acc[i][j] += aa[i] * bb[j];
        }
        __syncthreads();
    }

#pragma unroll
    for (int i = 0; i < 4; ++i) {
        int gi = i0 + ty * 4 + i;
        if (gi < NSEG) {
#pragma unroll
            for (int j = 0; j < 4; ++j) {
                int gj = j0 + tx * 4 + j;
                if (gj < NSEG)
                    g_aff[gi * NSEG + gj] = expf(-acc[i][j]);
            }
        }
    }
}

// ---------------- MLP tail: h3 = relu(h2@W3+b3); pred = softmax(h3@Wc+bc) -----
__global__ __launch_bounds__(256) void k_head(const float* __restrict__ W3,
                                              const float* __restrict__ b3,
                                              const float* __restrict__ Wc,
                                              const float* __restrict__ bc,
                                              float* __restrict__ out) {
    int r = blockIdx.x;
    int t = threadIdx.x;
    int n = t & 31;
    int ks = t >> 5;
    const float* h2r = g_h2 + (size_t)r * NH;

    float acc = 0.f;
    for (int kk = 0; kk < 128; ++kk) {
        int k = ks * 128 + kk;
        acc += h2r[k] * W3[k * 32 + n];
    }
    __shared__ float red[256];
    __shared__ float h3[32];
    red[t] = acc;
    __syncthreads();
    if (t < 32) {
        float v = red[t];
#pragma unroll
        for (int q = 1; q < 8; ++q) v += red[q * 32 + t];
        v += b3[t];
        h3[t] = fmaxf(v, 0.f);
    }
    __syncthreads();
    if (t == 0) {
        float l0 = bc[0], l1 = bc[1];
#pragma unroll
        for (int d = 0; d < 32; ++d) {
            l0 += h3[d] * Wc[d * 2 + 0];
            l1 += h3[d] * Wc[d * 2 + 1];
        }
        float m = fmaxf(l0, l1);
        float e0 = expf(l0 - m), e1 = expf(l1 - m);
        float inv = 1.f / (e0 + e1);
        out[r * 2 + 0] = e0 * inv;
        out[r * 2 + 1] = e1 * inv;
    }
}

// ---------------- label propagation: masked argmax over aff row ---------------
__global__ __launch_bounds__(128) void k_prop(float* __restrict__ out) {
    int i = blockIdx.x;
    int t = threadIdx.x;
    float bv = -INFINITY;
    int   bi = 0;
    for (int j = t; j < NSEG; j += 128) {
        if (g_lab[j] != 0) {
            float v = g_aff[i * NSEG + j];
            if (v > bv) { bv = v; bi = j; }
        }
    }
    __shared__ float sv[128];
    __shared__ int   si[128];
    sv[t] = bv; si[t] = bi;
    __syncthreads();
    for (int o = 64; o; o >>= 1) {
        if (t < o) {
            float v2 = sv[t + o]; int i2 = si[t + o];
            if (v2 > sv[t] || (v2 == sv[t] && i2 < si[t])) { sv[t] = v2; si[t] = i2; }
        }
        __syncthreads();
    }
    if (t == 0) {
        int li = g_lab[i];
        int nl = (li == 0 && sv[0] >= 0.7f) ? g_lab[si[0]] : li;
        out[880 + i] = (float)nl;
    }
}

// ---------------- launcher -----------------------------------------------------
extern "C" void kernel_launch(void* const* d_in, const int* in_sizes, int n_in,
                              void* d_out, int out_size) {
    const float* fm = (const float*)d_in[0];
    const int*   sp = (const int*)d_in[1];
    const int*   y  = (const int*)d_in[2];
    const float* W1 = (const float*)d_in[3];
    const float* b1 = (const float*)d_in[4];
    const float* W2 = (const float*)d_in[5];
    const float* b2 = (const float*)d_in[6];
    const float* W3 = (const float*)d_in[7];
    const float* b3 = (const float*)d_in[8];
    const float* Wc = (const float*)d_in[9];
    const float* bc = (const float*)d_in[10];
    float* out = (float*)d_out;

    void *p_feat, *p_h1, *p_h2;
    cudaGetSymbolAddress(&p_feat, g_feat);
    cudaGetSymbolAddress(&p_h1, g_h1);
    cudaGetSymbolAddress(&p_h2, g_h2);

    k_zero<<<6, 256>>>();
    k_hist<<<HW / 256, 256>>>(sp, y);
    k_scan<<<1, 512>>>();
    k_scatter<<<HW / 256, 256>>>(sp);
    k_tr<<<dim3(HW / 32, NCH / 32), dim3(32, 8)>>>(fm);
    k_pool<<<NSEG, 256>>>();
    k_lab<<<2, 256>>>();

    // h1 = relu(feat @ W1 + b1) : (440 x 2112) @ (2112 x 1024)
    k_gemm_relu<<<dim3(NH / 64, (NSEG + 63) / 64), dim3(16, 16)>>>(
        (const float*)p_feat, W1, b1, (float*)p_h1, NSEG, NH, NCH);
    // h2 = relu(h1 @ W2 + b2) : (440 x 1024) @ (1024 x 1024)
    k_gemm_relu<<<dim3(NH / 64, (NSEG + 63) / 64), dim3(16, 16)>>>(
        (const float*)p_h1, W2, b2, (float*)p_h2, NSEG, NH, NH);

    k_head<<<NSEG, 256>>>(W3, b3, Wc, bc, out);
    k_aff<<<dim3((NSEG + 63) / 64, (NSEG + 63) / 64), dim3(16, 16)>>>();
    k_prop<<<NSEG, 128>>>(out);
}